// round 4
// baseline (speedup 1.0000x reference)
#include <cuda_runtime.h>
#include <math.h>

#define N_TOKENS 65536
#define EMB_DIM  128
#define NUM_EMB  1024

// Output tuple flattened scalar-wise in reference-return order:
// (e_latent_loss, quantized_st[N,D], perplexity, encodings[N,K])
#define OUT_LOSS 0
#define OUT_Q    1
#define OUT_PERP (1 + N_TOKENS * EMB_DIM)        // 8388609
#define OUT_ENC  (2 + N_TOKENS * EMB_DIM)        // 8388610 (even -> 8B-aligned)

#define BM 128
#define BN 128
#define BK 16
#define SAS 132          // sA row stride (floats), 16B-aligned rows
#define SBS 260          // sB row stride (floats, dup'd codes), 16B-aligned
#define NBLK (N_TOKENS / BM)   // 512

typedef unsigned long long u64;

__device__ float  g_be[NUM_EMB];     // fl32 of exact ||e_k||^2
__device__ float  g_sx[N_TOKENS];    // fl32 of exact ||x_n||^2
__device__ int    g_hist[NUM_EMB];   // code counts
__device__ double g_lpart[NBLK];     // per-block loss partials (deterministic)
__device__ unsigned int g_done;      // last-block-done counter

// packed f32x2 FMA: two independent exact fp32 RN FMAs per issue slot (FFMA2)
__device__ __forceinline__ u64 ffma2(u64 a, u64 b, u64 c) {
    u64 d;
    asm("fma.rn.f32x2 %0, %1, %2, %3;" : "=l"(d) : "l"(a), "l"(b), "l"(c));
    return d;
}
__device__ __forceinline__ void unpack2(u64 v, float& lo, float& hi) {
    asm("mov.b64 {%0, %1}, %2;" : "=f"(lo), "=f"(hi) : "l"(v));
}

// ---------------------------------------------------------------------------
// prep: codebook squared norms (double, order-insensitive) + zero hist/counter
// ---------------------------------------------------------------------------
__global__ void vq_prep_kernel(const float* __restrict__ emb) {
    int k = blockIdx.x * blockDim.x + threadIdx.x;
    if (k == 0) g_done = 0;
    if (k < NUM_EMB) {
        const float* e = emb + (size_t)k * EMB_DIM;
        double s = 0.0;
#pragma unroll
        for (int i = 0; i < EMB_DIM; i++) {
            double v = (double)e[i];
            s += v * v;
        }
        g_be[k]   = (float)s;
        g_hist[k] = 0;
    }
}

// ---------------------------------------------------------------------------
// per-token squared norms, double accumulation (order-insensitive)
// ---------------------------------------------------------------------------
__global__ void vq_sx_kernel(const float* __restrict__ x) {
    const int row  = blockIdx.x * 8 + (threadIdx.x >> 5);
    const int lane = threadIdx.x & 31;
    const float* xr = x + (size_t)row * EMB_DIM;
    double s = 0.0;
#pragma unroll
    for (int i = 0; i < 4; i++) {
        double v = (double)xr[lane + 32 * i];
        s += v * v;
    }
#pragma unroll
    for (int off = 16; off > 0; off >>= 1)
        s += __shfl_down_sync(0xffffffffu, s, off);
    if (lane == 0) g_sx[row] = (float)s;
}

// ---------------------------------------------------------------------------
// main: FFMA2-packed tiled GEMM (x @ emb^T). Each (token,code) dot is a strict
// sequential fp32 FMA chain over k ascending (one f32x2 lane). Distance uses
// the reference's exact rounding:  d = fl( fl(sx + se_k) - fl(2*dot) ).
// Token pairs share a f32x2 register; B tile stored lane-duplicated in smem.
// Epilogue: argmin reduce, one-hot, histogram, quantized_st, loss; the last
// block to finish also computes perplexity + loss scalars.
// ---------------------------------------------------------------------------
__global__ __launch_bounds__(256, 2)
void vq_main_kernel(const float* __restrict__ x,
                    const float* __restrict__ emb,
                    float* __restrict__ out)
{
    __shared__ __align__(16) float smembuf[BK * SAS + BK * SBS];  // 25088 B
    float* sA = smembuf;               // [BK][SAS]  x tile, k-major
    float* sB = smembuf + BK * SAS;    // [BK][SBS]  emb tile, k-major, dup'd

    const int tid = threadIdx.x;       // 256 threads
    const int tx  = tid & 15;          // code lane: codes tx + 16*j
    const int ty  = tid >> 4;          // token-pair lane: pairs ty + 16*p
    const int m0  = blockIdx.x * BM;

    const int lr = tid >> 2;           // 0..63 : row within load pass
    const int lc = tid & 3;            // 0..3  : float4 column (16 k / 4)

    // ---- zero this block's one-hot region early (overlaps with GEMM) ----
    {
        float2* enc2 = (float2*)(out + OUT_ENC);
        size_t base = (size_t)m0 * (NUM_EMB / 2);
        for (int i = tid; i < BM * NUM_EMB / 2; i += 256)
            enc2[base + i] = make_float2(0.f, 0.f);
    }

    const float4* x4 = (const float4*)x;
    const float4* e4 = (const float4*)emb;

    // this thread's 8 tokens: local t = 2*(ty+16p) + q
    float sxr[4][2];
#pragma unroll
    for (int p = 0; p < 4; p++) {
        sxr[p][0] = g_sx[m0 + 2 * (ty + 16 * p) + 0];
        sxr[p][1] = g_sx[m0 + 2 * (ty + 16 * p) + 1];
    }

    float rmin[4][2];
    int   ridx[4][2];
#pragma unroll
    for (int p = 0; p < 4; p++)
#pragma unroll
        for (int q = 0; q < 2; q++) { rmin[p][q] = INFINITY; ridx[p][q] = 0; }

    u64 acc[4][8];

    // prefetch first tile (ct=0, ks=0)
    float4 va0 = x4[(size_t)(m0 + lr) * 32 + lc];
    float4 va1 = x4[(size_t)(m0 + 64 + lr) * 32 + lc];
    float4 vb0 = e4[(size_t)(lr) * 32 + lc];
    float4 vb1 = e4[(size_t)(64 + lr) * 32 + lc];

    for (int it = 0; it < 64; it++) {            // it = ct*8 + ks
        const int ct = it >> 3;
        const int ks = it & 7;
        const int k0 = ct * BN;

        __syncthreads();   // previous compute done; smem free
        // ---- store tile to smem (A transposed to k-major; B dup'd) ----
        {
            int kk = lc * 4;
            sA[(kk + 0) * SAS + lr] = va0.x;
            sA[(kk + 1) * SAS + lr] = va0.y;
            sA[(kk + 2) * SAS + lr] = va0.z;
            sA[(kk + 3) * SAS + lr] = va0.w;
            sA[(kk + 0) * SAS + 64 + lr] = va1.x;
            sA[(kk + 1) * SAS + 64 + lr] = va1.y;
            sA[(kk + 2) * SAS + 64 + lr] = va1.z;
            sA[(kk + 3) * SAS + 64 + lr] = va1.w;
            float2* b0 = (float2*)(sB + (kk + 0) * SBS);
            float2* b1 = (float2*)(sB + (kk + 1) * SBS);
            float2* b2 = (float2*)(sB + (kk + 2) * SBS);
            float2* b3 = (float2*)(sB + (kk + 3) * SBS);
            b0[lr] = make_float2(vb0.x, vb0.x);
            b1[lr] = make_float2(vb0.y, vb0.y);
            b2[lr] = make_float2(vb0.z, vb0.z);
            b3[lr] = make_float2(vb0.w, vb0.w);
            b0[64 + lr] = make_float2(vb1.x, vb1.x);
            b1[64 + lr] = make_float2(vb1.y, vb1.y);
            b2[64 + lr] = make_float2(vb1.z, vb1.z);
            b3[64 + lr] = make_float2(vb1.w, vb1.w);
        }
        __syncthreads();

        // ---- prefetch next tile from gmem (hidden behind compute) ----
        if (it < 63) {
            const int itn = it + 1;
            const int ksn = itn & 7;
            const int k0n = (itn >> 3) * BN;
            va0 = x4[(size_t)(m0 + lr) * 32 + ksn * 4 + lc];
            va1 = x4[(size_t)(m0 + 64 + lr) * 32 + ksn * 4 + lc];
            vb0 = e4[(size_t)(k0n + lr) * 32 + ksn * 4 + lc];
            vb1 = e4[(size_t)(k0n + 64 + lr) * 32 + ksn * 4 + lc];
        }

        if (ks == 0) {
#pragma unroll
            for (int p = 0; p < 4; p++)
#pragma unroll
                for (int j = 0; j < 8; j++) acc[p][j] = 0ull;
        }

        // ---- FFMA2 inner loop: k ascending, exact per-lane fp32 chain ----
#pragma unroll
        for (int k = 0; k < BK; k++) {
            const u64* ad = (const u64*)(sA + k * SAS);
            const u64* bd = (const u64*)(sB + k * SBS);
            u64 a0 = ad[ty];
            u64 a1 = ad[ty + 16];
            u64 a2 = ad[ty + 32];
            u64 a3 = ad[ty + 48];
            u64 b[8];
#pragma unroll
            for (int j = 0; j < 8; j++) b[j] = bd[tx + 16 * j];
#pragma unroll
            for (int j = 0; j < 8; j++) {
                acc[0][j] = ffma2(a0, b[j], acc[0][j]);
                acc[1][j] = ffma2(a1, b[j], acc[1][j]);
                acc[2][j] = ffma2(a2, b[j], acc[2][j]);
                acc[3][j] = ffma2(a3, b[j], acc[3][j]);
            }
        }

        // ---- end of ct: fold distances with reference rounding ----
        if (ks == 7) {
#pragma unroll
            for (int j = 0; j < 8; j++) {
                const int kk  = k0 + tx + 16 * j;   // j ascending => kk ascending
                const float bek = g_be[kk];
#pragma unroll
                for (int p = 0; p < 4; p++) {
                    float lo, hi;
                    unpack2(acc[p][j], lo, hi);
                    float d0 = __fsub_rn(__fadd_rn(sxr[p][0], bek),
                                         __fmul_rn(2.0f, lo));
                    float d1 = __fsub_rn(__fadd_rn(sxr[p][1], bek),
                                         __fmul_rn(2.0f, hi));
                    if (d0 < rmin[p][0]) { rmin[p][0] = d0; ridx[p][0] = kk; }
                    if (d1 < rmin[p][1]) { rmin[p][1] = d1; ridx[p][1] = kk; }
                }
            }
        }
    }

    // -------- cross-thread argmin reduction (16 tx-threads per token) --------
    __syncthreads();
    float*  redv = (float*)smembuf;                               // [0, 8192)
    int*    redi = (int*)   ((char*)smembuf + 8192);              // [8192, 16384)
    int*    s_bk = (int*)   ((char*)smembuf + 16384);             // [16384, 16896)
    double* lred = (double*)((char*)smembuf + 16896);             // [16896, 18944)
#pragma unroll
    for (int p = 0; p < 4; p++)
#pragma unroll
        for (int q = 0; q < 2; q++) {
            const int t = 2 * (ty + 16 * p) + q;
            redv[t * 16 + tx] = rmin[p][q];
            redi[t * 16 + tx] = ridx[p][q];
        }
    __syncthreads();

    if (tid < 128) {
        float bv = redv[tid * 16];
        int   bk = redi[tid * 16];
#pragma unroll
        for (int t = 1; t < 16; t++) {
            float v  = redv[tid * 16 + t];
            int   kk = redi[tid * 16 + t];
            if (v < bv || (v == bv && kk < bk)) { bv = v; bk = kk; }
        }
        s_bk[tid] = bk;
        const int row = m0 + tid;
        out[(size_t)OUT_ENC + (size_t)row * NUM_EMB + bk] = 1.0f;
        atomicAdd(&g_hist[bk], 1);   // integer atomic: deterministic
    }
    __syncthreads();

    // -------- cooperative coalesced quantized_st + loss (32-bit stores) ----
    double lsum = 0.0;
    float* oq = out + OUT_Q + (size_t)m0 * EMB_DIM;
    const float* xq = x + (size_t)m0 * EMB_DIM;
    for (int e = tid; e < BM * EMB_DIM; e += 256) {
        const int row = e >> 7;
        const int col = e & 127;
        const float xv = xq[e];
        const float qv = emb[(size_t)s_bk[row] * EMB_DIM + col];
        const float d  = __fsub_rn(qv, xv);
        oq[e] = __fadd_rn(xv, d);        // fl(x + fl(q-x)), exact STE math
        lsum += (double)d * (double)d;
    }
    lred[tid] = lsum;
    __syncthreads();
    for (int s = 128; s > 0; s >>= 1) {
        if (tid < s) lred[tid] += lred[tid + s];
        __syncthreads();
    }
    if (tid == 0) g_lpart[blockIdx.x] = lred[0];

    // -------- last block computes the scalars (fused finalize) --------
    __shared__ bool is_last;
    __threadfence();
    if (tid == 0) {
        unsigned v = atomicAdd(&g_done, 1u);
        is_last = (v == NBLK - 1);
    }
    __syncthreads();
    if (!is_last) return;

    // entropy over histogram (4 bins/thread, fixed order) + loss partial sum
    double ent = 0.0;
#pragma unroll
    for (int b = 0; b < 4; b++) {
        double pr = (double)g_hist[tid * 4 + b] / (double)N_TOKENS;
        ent += pr * log(pr + 1e-10);
    }
    double ls = 0.0;
#pragma unroll
    for (int b = 0; b < 2; b++) ls += g_lpart[tid * 2 + b];
    double* eacc = lred;                 // reuse [16896, 18944)
    double* lacc = lred + 256;           // needs 2048 more bytes: total 4096 < smem
    eacc[tid] = ent;
    lacc[tid] = ls;
    __syncthreads();
    for (int s = 128; s > 0; s >>= 1) {
        if (tid < s) { eacc[tid] += eacc[tid + s]; lacc[tid] += lacc[tid + s]; }
        __syncthreads();
    }
    if (tid == 0) {
        out[OUT_PERP] = (float)exp(-eacc[0]);
        out[OUT_LOSS] = (float)(lacc[0] / ((double)N_TOKENS * (double)EMB_DIM));
    }
}

// ---------------------------------------------------------------------------
extern "C" void kernel_launch(void* const* d_in, const int* in_sizes, int n_in,
                              void* d_out, int out_size) {
    const float* x   = (const float*)d_in[0];   // inputs [65536,128]
    const float* emb = (const float*)d_in[1];   // emb_w  [1024,128]
    float* out = (float*)d_out;

    vq_prep_kernel<<<(NUM_EMB + 255) / 256, 256>>>(emb);
    vq_sx_kernel<<<N_TOKENS / 8, 256>>>(x);
    vq_main_kernel<<<NBLK, 256>>>(x, emb, out);
}